// round 7
// baseline (speedup 1.0000x reference)
#include <cuda_runtime.h>
#include <cstdint>

#define N2    361
#define NTHR  256
#define WARPS 8
#define TS    1024
#define OVF   16
#define GXC   16
#define NEGV  (-1000000000.0f)
#define I32MIN_V (-2147483647 - 1)

__global__ __launch_bounds__(NTHR, 5)
void board_kernel(const float* __restrict__ logits,
                  const int* __restrict__ legal,      // bool as int32
                  const int* __restrict__ player,
                  const int* __restrict__ cur_hash,
                  const int* __restrict__ hist,
                  const int* __restrict__ move_count,
                  const int* __restrict__ ZposT,
                  const int* __restrict__ sgi,
                  const int* __restrict__ sp,
                  const int* __restrict__ gp,
                  const int* __restrict__ cap,
                  float* __restrict__ out,
                  int B, int G)
{
    __shared__ int sh_tab[WARPS][TS];    // per-warp exact hash table
    __shared__ int sh_gx[WARPS][GXC];    // per-warp group XORs
    __shared__ int sh_ovf[WARPS][OVF];
    __shared__ int sh_ovfn[WARPS];
    __shared__ int sh_zd[2][N2];         // placement deltas: [0]=black, [1]=white

    const int t = threadIdx.x;
    const int w = t >> 5;
    const int l = t & 31;

    // block init: placement-delta tables (ZposT is L2-hot)
    for (int i = t; i < N2; i += NTHR) {
        const int ze = ZposT[i];
        sh_zd[0][i] = ze ^ ZposT[N2 + i];
        sh_zd[1][i] = ze ^ ZposT[2 * N2 + i];
    }
    __syncthreads();

    const int b = blockIdx.x * WARPS + w;
    if (b >= B) return;

    // ---- clear this warp's table (8x STS.128 per lane) ----
    int4* tp = reinterpret_cast<int4*>(sh_tab[w]);
    #pragma unroll
    for (int k = 0; k < TS / 4 / 32; ++k)
        tp[k * 32 + l] = make_int4(-1, -1, -1, -1);
    if (l == 0) sh_ovfn[w] = 0;

    // ---- board scalars (broadcast loads) ----
    const int pl = player[b];
    const int ch = cur_hash[b];
    int mc = move_count[b];
    if (mc < 0)  mc = 0;
    if (mc > N2) mc = N2;

    // ---- fused group-XOR (lane < G) ----
    int G2 = G; if (G2 > GXC) G2 = GXC;
    if (l < G2) {
        const int r  = gp[b] + l;
        const int s0 = sp[r], s1v = sp[r + 1];
        const int opp = (2 - pl) * N2;    // Zobrist row 1 + (1 - pl)
        int acc = 0;
        for (int s = s0; s < s1v; ++s) {
            int si = sgi[s];
            si = si < 0 ? 0 : (si >= N2 ? N2 - 1 : si);
            acc ^= ZposT[opp + si] ^ ZposT[si];
        }
        sh_gx[w][l] = acc;
    }

    const size_t base = (size_t)b * N2;

    // ---- insert pass 1: plain STS into slot1 (collisions overwrite) ----
    int keys[12];
    #pragma unroll
    for (int j = 0; j < 12; ++j) {
        const int tt = l + 32 * j;
        const bool ins = (tt <= mc) && (tt < N2);   // mc < N2 always => sentinel present
        int key = 1;                                 // inert marker
        if (ins) key = (tt < mc) ? hist[base + tt] : I32MIN_V;
        keys[j] = ins ? key : 1;
        if (ins) {
            const unsigned h = (unsigned)key * 2654435761u;
            sh_tab[w][h >> 22] = key;
        }
        if (!ins) keys[j] = 1;                       // 1 never inserted as marker? (valid keys can be 1)
    }
    __syncwarp();

    // ---- insert pass 2: evicted keys -> slot2 via CAS, else overflow ----
    #pragma unroll
    for (int j = 0; j < 12; ++j) {
        const int tt = l + 32 * j;
        const bool ins = (tt <= mc) && (tt < N2);
        if (ins) {
            const int key = keys[j];
            const unsigned h = (unsigned)key * 2654435761u;
            if (sh_tab[w][h >> 22] != key) {
                const int s2 = (int)((h >> 12) & (TS - 1));
                const int prev = atomicCAS(&sh_tab[w][s2], -1, key);
                if (prev != -1 && prev != key) {
                    const int oi = atomicAdd(&sh_ovfn[w], 1);
                    if (oi < OVF) sh_ovf[w][oi] = key;
                }
            }
        }
    }
    __syncwarp();

    // ---- probe + output ----
    const int* zdrow = sh_zd[pl & 1];
    int ovn = sh_ovfn[w];
    const bool fb = (ovn > OVF);          // statistically unreachable safety net
    if (ovn > OVF) ovn = OVF;

    #pragma unroll
    for (int j = 0; j < 12; ++j) {
        const int tt = l + 32 * j;
        if (tt < N2) {
            const int4 c4 = *reinterpret_cast<const int4*>(cap + (base + tt) * 4);
            int cd = 0;
            if (c4.x >= 0) cd ^= sh_gx[w][c4.x & (GXC - 1)];
            if (c4.y >= 0) cd ^= sh_gx[w][c4.y & (GXC - 1)];
            if (c4.z >= 0) cd ^= sh_gx[w][c4.z & (GXC - 1)];
            if (c4.w >= 0) cd ^= sh_gx[w][c4.w & (GXC - 1)];

            const int cand = ch ^ zdrow[tt] ^ cd;

            const unsigned hh = (unsigned)cand * 2654435761u;
            bool rep = (sh_tab[w][hh >> 22] == cand) |
                       (sh_tab[w][(hh >> 12) & (TS - 1)] == cand);
            for (int i = 0; i < ovn; ++i) rep |= (sh_ovf[w][i] == cand);
            if (fb && !rep) {                         // exact global fallback
                rep = (cand == I32MIN_V);
                for (int q = 0; q < mc && !rep; ++q)
                    rep = (hist[base + q] == cand);
            }

            const float lg  = logits[base + tt];
            const int   lgl = legal[base + tt];
            out[base + tt] = ((lgl != 0) & !rep) ? lg : NEGV;
        }
    }
}

extern "C" void kernel_launch(void* const* d_in, const int* in_sizes, int n_in,
                              void* d_out, int out_size)
{
    const float* logits = (const float*)d_in[0];
    const int*   legal  = (const int*)d_in[1];
    const int*   player = (const int*)d_in[2];
    const int*   chash  = (const int*)d_in[3];
    const int*   hist   = (const int*)d_in[4];
    const int*   mcnt   = (const int*)d_in[5];
    const int*   zpos   = (const int*)d_in[6];
    const int*   sgi    = (const int*)d_in[7];
    const int*   sp     = (const int*)d_in[8];
    const int*   gp     = (const int*)d_in[9];
    const int*   cap    = (const int*)d_in[10];
    float*       out    = (float*)d_out;

    const int B = in_sizes[2];           // current_player: B elements
    const int R = in_sizes[8] - 1;       // stone_global_pointer: R+1
    const int G = R / B;                 // groups per board (uniform)

    const int grid = (B + WARPS - 1) / WARPS;
    board_kernel<<<grid, NTHR>>>(logits, legal, player, chash, hist, mcnt,
                                 zpos, sgi, sp, gp, cap, out, B, G);
}